// round 2
// baseline (speedup 1.0000x reference)
#include <cuda_runtime.h>
#include <math.h>

#define CLAMP_V 10000.0f
#define EPS_V   1e-8f
#define C_DIM   1024
#define H_DIM   4
#define DH      256
#define S_MAX   18
#define SH_N    72          // S*H
#define NCAP    100352

// ------------------------- device scratch (static, no allocs) ----------------
__device__ float    g_qp[S_MAX * C_DIM];            // projected+scaled queries
__device__ float    g_B[SH_N * C_DIM];              // score projection vectors (w_nkv folded)
__device__ float    g_inv[NCAP];                    // 1/(rms+eps) per row
__device__ float    g_scores[(size_t)NCAP * SH_N];  // scores, later softmax weights (in place)
__device__ unsigned g_maxbits[SH_N];
__device__ float    g_Z[SH_N];
__device__ float    g_u[SH_N * C_DIM];              // weighted kv accumulator
__device__ float    g_ubar[H_DIM * C_DIM];
__device__ float    g_obar[C_DIM];

// ------------------------------- helpers -------------------------------------
__device__ __forceinline__ float san(float v) {
    if (!(v == v)) return 0.f;                       // NaN -> 0
    return fminf(fmaxf(v, -CLAMP_V), CLAMP_V);       // +-inf -> clamp
}
__device__ __forceinline__ unsigned enc(float f) {
    unsigned u = __float_as_uint(f);
    return (u & 0x80000000u) ? ~u : (u | 0x80000000u);
}
__device__ __forceinline__ float dec(unsigned u) {
    return (u & 0x80000000u) ? __uint_as_float(u & 0x7fffffffu) : __uint_as_float(~u);
}
__device__ __forceinline__ unsigned f2tf(float f) {
    unsigned r;
    asm("cvt.rna.tf32.f32 %0, %1;" : "=r"(r) : "f"(f));
    return r;
}
__device__ __forceinline__ void mma8(float d[4], const unsigned a[4], const unsigned b[2]) {
    asm volatile(
        "mma.sync.aligned.m16n8k8.row.col.f32.tf32.tf32.f32 "
        "{%0,%1,%2,%3},{%4,%5,%6,%7},{%8,%9},{%0,%1,%2,%3};\n"
        : "+f"(d[0]), "+f"(d[1]), "+f"(d[2]), "+f"(d[3])
        : "r"(a[0]), "r"(a[1]), "r"(a[2]), "r"(a[3]), "r"(b[0]), "r"(b[1]));
}
__device__ __forceinline__ float block_reduce_sum(float v, float* red8) {
    #pragma unroll
    for (int o = 16; o > 0; o >>= 1) v += __shfl_xor_sync(0xffffffffu, v, o);
    int w = threadIdx.x >> 5, lane = threadIdx.x & 31;
    if (lane == 0) red8[w] = v;
    __syncthreads();
    float tot = 0.f;
    #pragma unroll
    for (int i = 0; i < 8; i++) tot += red8[i];
    return tot;
}

// ------------------------------- kernels -------------------------------------
__global__ void k_init() {
    int i = blockIdx.x * 256 + threadIdx.x;
    if (i < SH_N * C_DIM) g_u[i] = 0.f;
    if (i < SH_N) { g_maxbits[i] = enc(-3.0e38f); g_Z[i] = 0.f; }
}

// qp[s][j] = ( rmsnorm(seeds[s], w_nq) . Wq[j] + bq[j] ) / 16
__global__ void k_qp(const float* __restrict__ seeds, const float* __restrict__ w_nq,
                     const float* __restrict__ ipw, const float* __restrict__ ipb) {
    __shared__ __align__(16) float qrow[C_DIM];
    __shared__ float red8[8];
    int s = blockIdx.x, t = threadIdx.x;
    float ssq = 0.f;
    for (int i = t; i < C_DIM; i += 256) {
        float v = san(seeds[s * C_DIM + i]);
        qrow[i] = v;
        ssq += v * v;
    }
    __syncthreads();
    float tot = block_reduce_sum(ssq, red8);
    float inv = 1.f / (sqrtf(tot) * (1.0f / 32.0f) + EPS_V);
    __syncthreads();
    for (int i = t; i < C_DIM; i += 256) qrow[i] = w_nq[i] * qrow[i] * inv;
    __syncthreads();
    int j = blockIdx.y * 256 + t;
    const float4* wr = (const float4*)(ipw + (size_t)j * C_DIM);
    const float4* q4 = (const float4*)qrow;
    float acc = ipb[j];
    #pragma unroll 8
    for (int c = 0; c < C_DIM / 4; c++) {
        float4 a = wr[c]; float4 b = q4[c];
        acc += a.x * b.x + a.y * b.y + a.z * b.z + a.w * b.w;
    }
    g_qp[s * C_DIM + j] = acc * 0.0625f;
}

// B[sh][c] = w_nkv[c] * sum_d qp[s][h*DH+d] * Wk[h*DH+d][c]
__global__ void k_bmat(const float* __restrict__ ipw, const float* __restrict__ w_nkv) {
    __shared__ float qh[DH];
    int sh = blockIdx.x, t = threadIdx.x;
    int s = sh >> 2, h = sh & 3;
    qh[t] = g_qp[s * C_DIM + h * DH + t];   // blockDim = 256 == DH
    __syncthreads();
    int c = blockIdx.y * 256 + t;
    const float* wk = ipw + ((size_t)C_DIM + h * DH) * C_DIM + c;
    float acc = 0.f;
    #pragma unroll 8
    for (int d = 0; d < DH; d++) acc += qh[d] * wk[(size_t)d * C_DIM];
    g_B[sh * C_DIM + c] = w_nkv[c] * acc;
}

// Pass 1: per row n: sanitize, sumsq -> inv, scores[n][0..71] = inv * (xs . B[sh])
__global__ void __launch_bounds__(256) k_scores(const float* __restrict__ x, int N) {
    __shared__ __align__(16) float Xs[128][36];
    __shared__ __align__(16) float Bs[72][36];
    __shared__ float sinv[128];
    int t = threadIdx.x, w = t >> 5, lane = t & 31;
    size_t base = (size_t)blockIdx.x * 128;
    float acc[9][4];
    #pragma unroll
    for (int i = 0; i < 9; i++)
        #pragma unroll
        for (int j = 0; j < 4; j++) acc[i][j] = 0.f;
    float ssq = 0.f;
    int srow = t >> 1, shalf = (t & 1) * 16;

    for (int k0 = 0; k0 < C_DIM; k0 += 32) {
        #pragma unroll
        for (int it = 0; it < 4; it++) {
            int i = t + it * 256;
            int r = i >> 3, c4 = i & 7;
            size_t row = base + r;
            float4 v = make_float4(0.f, 0.f, 0.f, 0.f);
            if (row < (size_t)N) v = *(const float4*)(x + row * C_DIM + k0 + c4 * 4);
            v.x = san(v.x); v.y = san(v.y); v.z = san(v.z); v.w = san(v.w);
            *(float4*)&Xs[r][c4 * 4] = v;
        }
        for (int i = t; i < 576; i += 256) {
            int r = i >> 3, c4 = i & 7;
            float4 v = *(const float4*)(g_B + (size_t)r * C_DIM + k0 + c4 * 4);
            *(float4*)&Bs[r][c4 * 4] = v;
        }
        __syncthreads();
        #pragma unroll
        for (int j = 0; j < 4; j++) {
            float4 v = *(float4*)&Xs[srow][shalf + j * 4];
            ssq += v.x * v.x + v.y * v.y + v.z * v.z + v.w * v.w;
        }
        #pragma unroll
        for (int ks = 0; ks < 4; ks++) {
            int kk = ks * 8;
            int ar = w * 16 + (lane >> 2);
            int ac = kk + (lane & 3);
            unsigned a[4];
            a[0] = f2tf(Xs[ar][ac]);     a[1] = f2tf(Xs[ar + 8][ac]);
            a[2] = f2tf(Xs[ar][ac + 4]); a[3] = f2tf(Xs[ar + 8][ac + 4]);
            #pragma unroll
            for (int nt = 0; nt < 9; nt++) {
                int br = nt * 8 + (lane >> 2);
                unsigned b[2];
                b[0] = f2tf(Bs[br][ac]);
                b[1] = f2tf(Bs[br][ac + 4]);
                mma8(acc[nt], a, b);
            }
        }
        __syncthreads();
    }
    // combine sumsq halves (threads t and t^1 share a row)
    ssq += __shfl_xor_sync(0xffffffffu, ssq, 1);
    float inv = 1.f / (sqrtf(ssq) * (1.0f / 32.0f) + EPS_V);
    if ((t & 1) == 0) sinv[srow] = inv;
    __syncthreads();
    if ((t & 1) == 0 && base + srow < (size_t)N) g_inv[base + srow] = inv;

    int r0 = w * 16 + (lane >> 2);
    float iv0 = sinv[r0], iv1 = sinv[r0 + 8];
    size_t n0 = base + r0, n1 = n0 + 8;
    #pragma unroll
    for (int nt = 0; nt < 9; nt++) {
        int col = nt * 8 + 2 * (lane & 3);
        if (n0 < (size_t)N)
            *(float2*)&g_scores[n0 * SH_N + col] = make_float2(acc[nt][0] * iv0, acc[nt][1] * iv0);
        if (n1 < (size_t)N)
            *(float2*)&g_scores[n1 * SH_N + col] = make_float2(acc[nt][2] * iv1, acc[nt][3] * iv1);
    }
}

__global__ void k_max(int N) {
    __shared__ float sm[288];
    int t = threadIdx.x;
    int sh = t % 72, sub = t / 72;
    size_t per = ((size_t)N + gridDim.x - 1) / gridDim.x;
    size_t r0 = (size_t)blockIdx.x * per;
    size_t r1 = r0 + per; if (r1 > (size_t)N) r1 = N;
    float m = -3.0e38f;
    for (size_t r = r0 + sub; r < r1; r += 4) m = fmaxf(m, g_scores[r * SH_N + sh]);
    sm[t] = m;
    __syncthreads();
    if (sub == 0) {
        m = fmaxf(fmaxf(sm[sh], sm[sh + 72]), fmaxf(sm[sh + 144], sm[sh + 216]));
        atomicMax(&g_maxbits[sh], enc(m));
    }
}

__global__ void k_sumexp(int N) {
    __shared__ float sm[288];
    __shared__ float mxs[72];
    int t = threadIdx.x;
    int sh = t % 72, sub = t / 72;
    if (t < 72) mxs[t] = dec(g_maxbits[t]);
    __syncthreads();
    size_t per = ((size_t)N + gridDim.x - 1) / gridDim.x;
    size_t r0 = (size_t)blockIdx.x * per;
    size_t r1 = r0 + per; if (r1 > (size_t)N) r1 = N;
    float m = mxs[sh];
    float z = 0.f;
    for (size_t r = r0 + sub; r < r1; r += 4) z += __expf(g_scores[r * SH_N + sh] - m);
    sm[t] = z;
    __syncthreads();
    if (sub == 0) atomicAdd(&g_Z[sh], sm[sh] + sm[sh + 72] + sm[sh + 144] + sm[sh + 216]);
}

__global__ void k_wts(int N) {
    __shared__ float mxs[72], rz[72];
    int t = threadIdx.x;
    if (t < 72) { mxs[t] = dec(g_maxbits[t]); rz[t] = 1.f / g_Z[t]; }
    __syncthreads();
    size_t total = (size_t)N * SH_N;
    for (size_t i = (size_t)blockIdx.x * 256 + t; i < total; i += (size_t)gridDim.x * 256) {
        int sh = (int)(i % SH_N);
        g_scores[i] = __expf(g_scores[i] - mxs[sh]) * rz[sh];
    }
}

// Pass 2: u[sh][c] += sum_n w[sh,n] * inv[n] * xs[n,c]   (tf32 mma, atomic combine)
__global__ void __launch_bounds__(256) k_u(const float* __restrict__ x, int N) {
    __shared__ float Ws[32][88];
    __shared__ __align__(16) float Xs[32][72];
    int t = threadIdx.x, w = t >> 5, lane = t & 31;
    int cbase = blockIdx.x * 64;
    size_t per = ((size_t)N + gridDim.y - 1) / gridDim.y;
    size_t r0 = (size_t)blockIdx.y * per;
    size_t r1 = r0 + per; if (r1 > (size_t)N) r1 = N;
    float acc[5][4];
    #pragma unroll
    for (int i = 0; i < 5; i++)
        #pragma unroll
        for (int j = 0; j < 4; j++) acc[i][j] = 0.f;

    for (size_t k0 = r0; k0 < r1; k0 += 32) {
        #pragma unroll
        for (int it = 0; it < 10; it++) {
            int i = t + it * 256;            // 0..2559 : 32 rows x 80 padded sh
            int k = i / 80, sh = i % 80;
            size_t row = k0 + k;
            float v = 0.f;
            if (row < r1 && sh < 72) v = g_scores[row * SH_N + sh];
            Ws[k][sh] = v;
        }
        #pragma unroll
        for (int it = 0; it < 2; it++) {
            int i = t + it * 256;            // 0..511 float4 : 32 rows x 16 f4
            int k = i >> 4, c4 = i & 15;
            size_t row = k0 + k;
            float4 v = make_float4(0.f, 0.f, 0.f, 0.f);
            if (row < r1) {
                float iv = g_inv[row];
                v = *(const float4*)(x + row * C_DIM + cbase + c4 * 4);
                v.x = san(v.x) * iv; v.y = san(v.y) * iv;
                v.z = san(v.z) * iv; v.w = san(v.w) * iv;
            }
            *(float4*)&Xs[k][c4 * 4] = v;
        }
        __syncthreads();
        #pragma unroll
        for (int ks = 0; ks < 4; ks++) {
            int kA = ks * 8 + (lane & 3);
            int bc = w * 8 + (lane >> 2);
            unsigned b[2];
            b[0] = f2tf(Xs[kA][bc]);
            b[1] = f2tf(Xs[kA + 4][bc]);
            #pragma unroll
            for (int mt = 0; mt < 5; mt++) {
                int m0 = mt * 16 + (lane >> 2);
                unsigned a[4];
                a[0] = f2tf(Ws[kA][m0]);     a[1] = f2tf(Ws[kA][m0 + 8]);
                a[2] = f2tf(Ws[kA + 4][m0]); a[3] = f2tf(Ws[kA + 4][m0 + 8]);
                mma8(acc[mt], a, b);
            }
        }
        __syncthreads();
    }
    #pragma unroll
    for (int mt = 0; mt < 5; mt++) {
        int row = mt * 16 + (lane >> 2);
        int col = cbase + w * 8 + 2 * (lane & 3);
        if (row < 72) {
            atomicAdd(&g_u[row * C_DIM + col],     acc[mt][0]);
            atomicAdd(&g_u[row * C_DIM + col + 1], acc[mt][1]);
        }
        if (row + 8 < 72) {
            atomicAdd(&g_u[(row + 8) * C_DIM + col],     acc[mt][2]);
            atomicAdd(&g_u[(row + 8) * C_DIM + col + 1], acc[mt][3]);
        }
    }
}

// ubar[h][c] = w_nkv[c] * mean_s u[(s,h)][c]
__global__ void k_ubar(const float* __restrict__ w_nkv, int S) {
    int i = blockIdx.x * 256 + threadIdx.x;
    if (i >= H_DIM * C_DIM) return;
    int h = i >> 10, c = i & 1023;
    float s = 0.f;
    for (int si = 0; si < S; si++) s += g_u[(size_t)(si * H_DIM + h) * C_DIM + c];
    g_ubar[i] = w_nkv[c] * s / (float)S;
}

// obar[j] = sum_c ubar[h][c] * Wv[2C+j][c] + bv[2C+j]
__global__ void k_obar(const float* __restrict__ ipw, const float* __restrict__ ipb) {
    __shared__ float red8[8];
    int j = blockIdx.x, t = threadIdx.x;
    int h = j >> 8;
    const float* wv = ipw + ((size_t)2 * C_DIM + j) * C_DIM;
    const float* ub = g_ubar + h * C_DIM;
    float acc = 0.f;
    for (int c = t; c < C_DIM; c += 256) acc += ub[c] * wv[c];
    float tot = block_reduce_sum(acc, red8);
    if (t == 0) g_obar[j] = tot + ipb[2 * C_DIM + j];
}

// out[c] = sanitize( sum_j obar[j] * Wout[c][j] + bout[c] )
__global__ void k_out(const float* __restrict__ opw, const float* __restrict__ opb,
                      float* __restrict__ out) {
    __shared__ float red8[8];
    int c = blockIdx.x, t = threadIdx.x;
    const float* wr = opw + (size_t)c * C_DIM;
    float acc = 0.f;
    for (int j = t; j < C_DIM; j += 256) acc += g_obar[j] * wr[j];
    float tot = block_reduce_sum(acc, red8);
    if (t == 0) out[c] = san(tot + opb[c]);
}

// ------------------------------- launcher ------------------------------------
extern "C" void kernel_launch(void* const* d_in, const int* in_sizes, int n_in,
                              void* d_out, int out_size) {
    const float* x     = (const float*)d_in[0];
    const float* seeds = (const float*)d_in[1];
    const float* w_nq  = (const float*)d_in[2];
    const float* w_nkv = (const float*)d_in[3];
    const float* ipw   = (const float*)d_in[4];
    const float* ipb   = (const float*)d_in[5];
    const float* opw   = (const float*)d_in[6];
    const float* opb   = (const float*)d_in[7];
    float* out = (float*)d_out;

    int N = in_sizes[0] / C_DIM;
    if (N > NCAP) N = NCAP;
    int S = in_sizes[1] / C_DIM;   // 18

    k_init<<<(SH_N * C_DIM + 255) / 256, 256>>>();
    k_qp<<<dim3(S, 4), 256>>>(seeds, w_nq, ipw, ipb);
    k_bmat<<<dim3(SH_N, 4), 256>>>(ipw, w_nkv);
    k_scores<<<(N + 127) / 128, 256>>>(x, N);
    k_max<<<128, 288>>>(N);
    k_sumexp<<<128, 288>>>(N);
    k_wts<<<1024, 256>>>(N);
    k_u<<<dim3(16, 26), 256>>>(x, N);
    k_ubar<<<(H_DIM * C_DIM + 255) / 256, 256>>>(w_nkv, S);
    k_obar<<<C_DIM, 256>>>(ipw, ipb);
    k_out<<<C_DIM, 256>>>(opw, opb, out);
}

// round 3
// speedup vs baseline: 1.7576x; 1.7576x over previous
#include <cuda_runtime.h>
#include <math.h>
#include <stdint.h>

#define CLAMP_V 10000.0f
#define EPS_V   1e-8f
#define C_DIM   1024
#define H_DIM   4
#define DH      256
#define S_MAX   18
#define SH_N    72          // S*H
#define SH_P    80          // padded to 5 m16 tiles
#define NCAP    100352
#define GCAP    (NCAP/8)

// ------------------------- device scratch (static, no allocs) ----------------
__device__ float    g_qp[S_MAX * C_DIM];
__device__ uint2    g_Bp[128 * SH_N * 4];            // [kg][sh][j] tf32 pairs (k, k+4)
__device__ float    g_inv[NCAP];
__device__ float    g_scores[(size_t)NCAP * SH_N];   // raw scores [n][sh]
__device__ uint2    g_Wp[(size_t)GCAP * SH_P * 4];   // [g][sh][j] tf32 weight pairs
__device__ unsigned g_maxbits[SH_N];
__device__ float    g_Z[SH_N];
__device__ float    g_u[SH_N * C_DIM];
__device__ float    g_ubar[H_DIM * C_DIM];
__device__ float    g_obar[C_DIM];

// ------------------------------- helpers -------------------------------------
__device__ __forceinline__ float san(float v) {
    if (!(v == v)) return 0.f;
    return fminf(fmaxf(v, -CLAMP_V), CLAMP_V);
}
__device__ __forceinline__ unsigned enc(float f) {
    unsigned u = __float_as_uint(f);
    return (u & 0x80000000u) ? ~u : (u | 0x80000000u);
}
__device__ __forceinline__ float dec(unsigned u) {
    return (u & 0x80000000u) ? __uint_as_float(u & 0x7fffffffu) : __uint_as_float(~u);
}
__device__ __forceinline__ unsigned f2tf(float f) {
    unsigned r;
    asm("cvt.rna.tf32.f32 %0, %1;" : "=r"(r) : "f"(f));
    return r;
}
__device__ __forceinline__ void mma8(float d[4], const unsigned a[4], const unsigned b[2]) {
    asm volatile(
        "mma.sync.aligned.m16n8k8.row.col.f32.tf32.tf32.f32 "
        "{%0,%1,%2,%3},{%4,%5,%6,%7},{%8,%9},{%0,%1,%2,%3};\n"
        : "+f"(d[0]), "+f"(d[1]), "+f"(d[2]), "+f"(d[3])
        : "r"(a[0]), "r"(a[1]), "r"(a[2]), "r"(a[3]), "r"(b[0]), "r"(b[1]));
}
__device__ __forceinline__ float block_reduce_sum(float v, float* red8) {
    #pragma unroll
    for (int o = 16; o > 0; o >>= 1) v += __shfl_xor_sync(0xffffffffu, v, o);
    int w = threadIdx.x >> 5, lane = threadIdx.x & 31;
    if (lane == 0) red8[w] = v;
    __syncthreads();
    float tot = 0.f;
    #pragma unroll
    for (int i = 0; i < 8; i++) tot += red8[i];
    return tot;
}

// ------------------------------- kernels -------------------------------------
__global__ void k_init() {
    int i = blockIdx.x * 256 + threadIdx.x;
    if (i < SH_N * C_DIM) g_u[i] = 0.f;
    if (i < SH_N) { g_maxbits[i] = enc(-3.0e38f); g_Z[i] = 0.f; }
}

// qp[s][j] = ( rmsnorm(seeds[s], w_nq) . Wq[j] + bq[j] ) / 16
__global__ void k_qp(const float* __restrict__ seeds, const float* __restrict__ w_nq,
                     const float* __restrict__ ipw, const float* __restrict__ ipb) {
    __shared__ __align__(16) float qrow[C_DIM];
    __shared__ float red8[8];
    int s = blockIdx.x, t = threadIdx.x;
    float ssq = 0.f;
    for (int i = t; i < C_DIM; i += 256) {
        float v = san(seeds[s * C_DIM + i]);
        qrow[i] = v;
        ssq += v * v;
    }
    __syncthreads();
    float tot = block_reduce_sum(ssq, red8);
    float inv = 1.f / (sqrtf(tot) * (1.0f / 32.0f) + EPS_V);
    __syncthreads();
    for (int i = t; i < C_DIM; i += 256) qrow[i] = w_nq[i] * qrow[i] * inv;
    __syncthreads();
    int j = blockIdx.y * 256 + t;
    const float4* wr = (const float4*)(ipw + (size_t)j * C_DIM);
    const float4* q4 = (const float4*)qrow;
    float acc = ipb[j];
    #pragma unroll 8
    for (int c = 0; c < C_DIM / 4; c++) {
        float4 a = wr[c]; float4 b = q4[c];
        acc += a.x * b.x + a.y * b.y + a.z * b.z + a.w * b.w;
    }
    g_qp[s * C_DIM + j] = acc * 0.0625f;
}

// B[sh][c] = w_nkv[c] * sum_d qp[s][h*DH+d] * Wk[h*DH+d][c]   -> packed tf32 pairs
__global__ void k_bmat(const float* __restrict__ ipw, const float* __restrict__ w_nkv) {
    __shared__ float qh[DH];
    int sh = blockIdx.x, t = threadIdx.x;
    int s = sh >> 2, h = sh & 3;
    qh[t] = g_qp[s * C_DIM + h * DH + t];   // blockDim = 256 == DH
    __syncthreads();
    int c = blockIdx.y * 256 + t;
    const float* wk = ipw + ((size_t)C_DIM + h * DH) * C_DIM + c;
    float acc = 0.f;
    #pragma unroll 8
    for (int d = 0; d < DH; d++) acc += qh[d] * wk[(size_t)d * C_DIM];
    float v = w_nkv[c] * acc;
    float v4 = __shfl_down_sync(0xffffffffu, v, 4);
    if ((c & 7) < 4) {
        int kg = c >> 3, j = c & 3;
        g_Bp[((size_t)kg * SH_N + sh) * 4 + j] = make_uint2(f2tf(v), f2tf(v4));
    }
}

// Pass 1: per row n: sanitize, sumsq -> inv, scores[n][0..71] = inv * (xs . B[sh])
__global__ void __launch_bounds__(256) k_scores(const float* __restrict__ x, int N) {
    __shared__ __align__(16) uint2 Xs[4][128][4];   // [kg][row][j] pairs (k, k+4)
    __shared__ __align__(16) uint2 Bs[4][SH_N][4];
    __shared__ float ssq2[256];
    __shared__ float sinv[128];
    int t = threadIdx.x, w = t >> 5, lane = t & 31;
    size_t base = (size_t)blockIdx.x * 128;
    int rowL = t & 127;
    int kgA = t >> 7;                 // this thread stages kgs {kgA, kgA+2} of its row
    size_t grow = base + rowL;
    bool rok = grow < (size_t)N;
    const float* xr = x + grow * C_DIM;
    float acc[9][4];
    #pragma unroll
    for (int i = 0; i < 9; i++)
        #pragma unroll
        for (int j = 0; j < 4; j++) acc[i][j] = 0.f;
    float ssq = 0.f;

    for (int k0 = 0; k0 < C_DIM; k0 += 32) {
        // stage B chunk (contiguous copy of pre-packed tf32 pairs)
        {
            const uint2* src = g_Bp + (size_t)(k0 >> 3) * SH_N * 4;
            uint2* dst = (uint2*)Bs;
            #pragma unroll
            for (int i = 0; i < 5; i++) {
                int idx = t + i * 256;
                if (idx < 4 * SH_N * 4) dst[idx] = src[idx];
            }
        }
        // stage X chunk: sanitize, sumsq, tf32-round, pack pairs
        #pragma unroll
        for (int half = 0; half < 2; half++) {
            int kg = kgA + half * 2;
            float4 fa = make_float4(0.f, 0.f, 0.f, 0.f);
            float4 fb = make_float4(0.f, 0.f, 0.f, 0.f);
            if (rok) {
                fa = *(const float4*)(xr + k0 + kg * 8);
                fb = *(const float4*)(xr + k0 + kg * 8 + 4);
            }
            fa.x = san(fa.x); fa.y = san(fa.y); fa.z = san(fa.z); fa.w = san(fa.w);
            fb.x = san(fb.x); fb.y = san(fb.y); fb.z = san(fb.z); fb.w = san(fb.w);
            ssq += fa.x * fa.x + fa.y * fa.y + fa.z * fa.z + fa.w * fa.w
                 + fb.x * fb.x + fb.y * fb.y + fb.z * fb.z + fb.w * fb.w;
            uint4* dst = (uint4*)&Xs[kg][rowL][0];
            dst[0] = make_uint4(f2tf(fa.x), f2tf(fb.x), f2tf(fa.y), f2tf(fb.y));
            dst[1] = make_uint4(f2tf(fa.z), f2tf(fb.z), f2tf(fa.w), f2tf(fb.w));
        }
        __syncthreads();
        #pragma unroll
        for (int ks = 0; ks < 4; ks++) {
            int ar = w * 16 + (lane >> 2);
            int j = lane & 3;
            uint2 xa = Xs[ks][ar][j];
            uint2 xb = Xs[ks][ar + 8][j];
            unsigned a[4] = {xa.x, xb.x, xa.y, xb.y};
            #pragma unroll
            for (int nt = 0; nt < 9; nt++) {
                uint2 bb = Bs[ks][nt * 8 + (lane >> 2)][j];
                unsigned b[2] = {bb.x, bb.y};
                mma8(acc[nt], a, b);
            }
        }
        __syncthreads();
    }
    ssq2[t] = ssq;
    __syncthreads();
    if (t < 128) {
        float tot = ssq2[t] + ssq2[t + 128];
        float inv = 1.f / (sqrtf(tot) * (1.0f / 32.0f) + EPS_V);
        sinv[t] = inv;
        if (base + t < (size_t)N) g_inv[base + t] = inv;
    }
    __syncthreads();
    int r0 = w * 16 + (lane >> 2);
    float iv0 = sinv[r0], iv1 = sinv[r0 + 8];
    size_t n0 = base + r0, n1 = n0 + 8;
    #pragma unroll
    for (int nt = 0; nt < 9; nt++) {
        int col = nt * 8 + 2 * (lane & 3);
        if (n0 < (size_t)N)
            *(float2*)&g_scores[n0 * SH_N + col] = make_float2(acc[nt][0] * iv0, acc[nt][1] * iv0);
        if (n1 < (size_t)N)
            *(float2*)&g_scores[n1 * SH_N + col] = make_float2(acc[nt][2] * iv1, acc[nt][3] * iv1);
    }
}

__global__ void k_max(int N) {
    __shared__ float sm[288];
    int t = threadIdx.x;
    int sh = t % 72, sub = t / 72;
    size_t per = ((size_t)N + gridDim.x - 1) / gridDim.x;
    size_t r0 = (size_t)blockIdx.x * per;
    size_t r1 = r0 + per; if (r1 > (size_t)N) r1 = N;
    float m = -3.0e38f;
    for (size_t r = r0 + sub; r < r1; r += 4) m = fmaxf(m, g_scores[r * SH_N + sh]);
    sm[t] = m;
    __syncthreads();
    if (sub == 0) {
        m = fmaxf(fmaxf(sm[sh], sm[sh + 72]), fmaxf(sm[sh + 144], sm[sh + 216]));
        atomicMax(&g_maxbits[sh], enc(m));
    }
}

__global__ void k_sumexp(int N) {
    __shared__ float sm[288];
    __shared__ float mxs[72];
    int t = threadIdx.x;
    int sh = t % 72, sub = t / 72;
    if (t < 72) mxs[t] = dec(g_maxbits[t]);
    __syncthreads();
    size_t per = ((size_t)N + gridDim.x - 1) / gridDim.x;
    size_t r0 = (size_t)blockIdx.x * per;
    size_t r1 = r0 + per; if (r1 > (size_t)N) r1 = N;
    float m = mxs[sh];
    float z = 0.f;
    for (size_t r = r0 + sub; r < r1; r += 4) z += __expf(g_scores[r * SH_N + sh] - m);
    sm[t] = z;
    __syncthreads();
    if (sub == 0) atomicAdd(&g_Z[sh], sm[sh] + sm[sh + 72] + sm[sh + 144] + sm[sh + 216]);
}

// softmax weights, tf32-rounded, packed as MMA-A fragment pairs over the n dim
__global__ void k_pack(int N) {
    __shared__ float sm[64 * SH_N];
    __shared__ float mxs[SH_N], rz[SH_N];
    int t = threadIdx.x;
    if (t < SH_N) { mxs[t] = dec(g_maxbits[t]); rz[t] = 1.f / g_Z[t]; }
    int G = N >> 3;
    int g0 = blockIdx.x * 8;
    if (g0 >= G) return;
    int ng = G - g0; if (ng > 8) ng = 8;
    size_t row0 = (size_t)g0 * 8;
    int cnt = ng * 8 * SH_N;
    for (int i = t; i < cnt; i += 256) sm[i] = g_scores[row0 * SH_N + i];
    __syncthreads();
    int total = ng * SH_P * 4;
    for (int i = t; i < total; i += 256) {
        int gg = i / (SH_P * 4);
        int r = i - gg * (SH_P * 4);
        int sh = r >> 2, j = r & 3;
        float w0 = 0.f, w1 = 0.f;
        if (sh < SH_N) {
            float m = mxs[sh], z = rz[sh];
            w0 = __expf(sm[(gg * 8 + j) * SH_N + sh] - m) * z;
            w1 = __expf(sm[(gg * 8 + j + 4) * SH_N + sh] - m) * z;
        }
        g_Wp[((size_t)(g0 + gg) * SH_P) * 4 + r] = make_uint2(f2tf(w0), f2tf(w1));
    }
}

// Pass 2: u[sh][c] += sum_n w[sh,n] * inv[n] * xs[n,c]
#define UY 37
__global__ void __launch_bounds__(256) k_u(const float* __restrict__ x, int N) {
    __shared__ __align__(16) uint2 Ws[4][SH_P][4];      // [g][sh][j]
    __shared__ __align__(16) unsigned Xs[32][136];      // tf32 vals, padded stride
    int t = threadIdx.x, w = t >> 5, lane = t & 31;
    int cbase = blockIdx.x * 128;
    int TC = N >> 5;
    int c0 = (int)((size_t)blockIdx.y * TC / UY);
    int c1 = (int)((size_t)(blockIdx.y + 1) * TC / UY);
    float acc[5][2][4];
    #pragma unroll
    for (int i = 0; i < 5; i++)
        #pragma unroll
        for (int j = 0; j < 2; j++)
            #pragma unroll
            for (int k = 0; k < 4; k++) acc[i][j][k] = 0.f;

    for (int ch = c0; ch < c1; ch++) {
        size_t n0 = (size_t)ch * 32;
        {
            const uint2* src = g_Wp + (n0 >> 3) * SH_P * 4;
            uint2* dst = (uint2*)Ws;
            #pragma unroll
            for (int i = 0; i < 5; i++) dst[t + i * 256] = src[t + i * 256];
        }
        #pragma unroll
        for (int it = 0; it < 4; it++) {
            int f = t + it * 256;
            int row = f >> 5, c4 = f & 31;
            float iv = g_inv[n0 + row];
            float4 v = *(const float4*)(x + (n0 + row) * C_DIM + cbase + c4 * 4);
            v.x = san(v.x) * iv; v.y = san(v.y) * iv;
            v.z = san(v.z) * iv; v.w = san(v.w) * iv;
            *(uint4*)&Xs[row][c4 * 4] = make_uint4(f2tf(v.x), f2tf(v.y), f2tf(v.z), f2tf(v.w));
        }
        __syncthreads();
        #pragma unroll
        for (int g = 0; g < 4; g++) {
            int j = lane & 3, q = lane >> 2;
            unsigned a[5][4];
            #pragma unroll
            for (int mt = 0; mt < 5; mt++) {
                uint2 wa = Ws[g][mt * 16 + q][j];
                uint2 wb = Ws[g][mt * 16 + 8 + q][j];
                a[mt][0] = wa.x; a[mt][1] = wb.x; a[mt][2] = wa.y; a[mt][3] = wb.y;
            }
            #pragma unroll
            for (int ct = 0; ct < 2; ct++) {
                int col = w * 16 + ct * 8 + q;
                int kA = g * 8 + j;
                unsigned b[2] = { Xs[kA][col], Xs[kA + 4][col] };
                #pragma unroll
                for (int mt = 0; mt < 5; mt++) mma8(acc[mt][ct], a[mt], b);
            }
        }
        __syncthreads();
    }
    #pragma unroll
    for (int mt = 0; mt < 5; mt++) {
        int sh = mt * 16 + (lane >> 2);
        #pragma unroll
        for (int ct = 0; ct < 2; ct++) {
            int c = cbase + w * 16 + ct * 8 + 2 * (lane & 3);
            if (sh < SH_N) {
                atomicAdd(&g_u[sh * C_DIM + c],     acc[mt][ct][0]);
                atomicAdd(&g_u[sh * C_DIM + c + 1], acc[mt][ct][1]);
            }
            if (sh + 8 < SH_N) {
                atomicAdd(&g_u[(sh + 8) * C_DIM + c],     acc[mt][ct][2]);
                atomicAdd(&g_u[(sh + 8) * C_DIM + c + 1], acc[mt][ct][3]);
            }
        }
    }
}

// ubar[h][c] = w_nkv[c] * mean_s u[(s,h)][c]
__global__ void k_ubar(const float* __restrict__ w_nkv, int S) {
    int i = blockIdx.x * 256 + threadIdx.x;
    if (i >= H_DIM * C_DIM) return;
    int h = i >> 10, c = i & 1023;
    float s = 0.f;
    for (int si = 0; si < S; si++) s += g_u[(size_t)(si * H_DIM + h) * C_DIM + c];
    g_ubar[i] = w_nkv[c] * s / (float)S;
}

// obar[j] = sum_c ubar[h][c] * Wv[2C+j][c] + bv[2C+j]
__global__ void k_obar(const float* __restrict__ ipw, const float* __restrict__ ipb) {
    __shared__ float red8[8];
    int j = blockIdx.x, t = threadIdx.x;
    int h = j >> 8;
    const float* wv = ipw + ((size_t)2 * C_DIM + j) * C_DIM;
    const float* ub = g_ubar + h * C_DIM;
    float acc = 0.f;
    for (int c = t; c < C_DIM; c += 256) acc += ub[c] * wv[c];
    float tot = block_reduce_sum(acc, red8);
    if (t == 0) g_obar[j] = tot + ipb[2 * C_DIM + j];
}

// out[c] = sanitize( sum_j obar[j] * Wout[c][j] + bout[c] )
__global__ void k_out(const float* __restrict__ opw, const float* __restrict__ opb,
                      float* __restrict__ out) {
    __shared__ float red8[8];
    int c = blockIdx.x, t = threadIdx.x;
    const float* wr = opw + (size_t)c * C_DIM;
    float acc = 0.f;
    for (int j = t; j < C_DIM; j += 256) acc += g_obar[j] * wr[j];
    float tot = block_reduce_sum(acc, red8);
    if (t == 0) out[c] = san(tot + opb[c]);
}

// ------------------------------- launcher ------------------------------------
extern "C" void kernel_launch(void* const* d_in, const int* in_sizes, int n_in,
                              void* d_out, int out_size) {
    const float* x     = (const float*)d_in[0];
    const float* seeds = (const float*)d_in[1];
    const float* w_nq  = (const float*)d_in[2];
    const float* w_nkv = (const float*)d_in[3];
    const float* ipw   = (const float*)d_in[4];
    const float* ipb   = (const float*)d_in[5];
    const float* opw   = (const float*)d_in[6];
    const float* opb   = (const float*)d_in[7];
    float* out = (float*)d_out;

    int N = in_sizes[0] / C_DIM;
    if (N > NCAP) N = NCAP;
    int S = in_sizes[1] / C_DIM;   // 18

    k_init<<<(SH_N * C_DIM + 255) / 256, 256>>>();
    k_qp<<<dim3(S, 4), 256>>>(seeds, w_nq, ipw, ipb);
    k_bmat<<<dim3(SH_N, 4), 256>>>(ipw, w_nkv);
    k_scores<<<(N + 127) / 128, 256>>>(x, N);
    k_max<<<128, 288>>>(N);
    k_sumexp<<<128, 288>>>(N);
    k_pack<<<((N >> 3) + 7) / 8, 256>>>(N);
    k_u<<<dim3(8, UY), 256>>>(x, N);
    k_ubar<<<(H_DIM * C_DIM + 255) / 256, 256>>>(w_nkv, S);
    k_obar<<<C_DIM, 256>>>(ipw, ipb);
    k_out<<<C_DIM, 256>>>(opw, opb, out);
}